// round 9
// baseline (speedup 1.0000x reference)
#include <cuda_runtime.h>
#include <cstdint>

// Problem constants (fixed by the reference)
#define B 4096      // batch
#define G 20000     // genes (K)
#define J 5000      // GO terms (N)
#define CAP 64      // max nnz per column overall (~Poisson(16), max ~40)
#define TCAP 32     // max nnz per column per gene-third (~Poisson(5.3))
#define NB (CAP + 1)

// gene segments: [0,6672) [6672,13344) [13344,20000)
#define SEG0 6672
#define SEG1 6672
#define SEG2 6656
#define SEGMAX 6672

#define TPB 512
#define RPB 4                        // batch rows per SpMM block
#define CPT 10                       // ceil(J / TPB) columns per thread
#define SMEM_BYTES (SEGMAX * 16)     // 106,752 B -> 2 CTAs/SM

// Static device scratch (no allocation allowed anywhere)
__device__ int      g_cnt[J];
__device__ uint16_t g_idx_u[CAP * J];          // unsorted ELL  [e][j]
__device__ float    g_val_u[CAP * J];
__device__ int      g_hist[NB];
__device__ int      g_off[NB];
__device__ int      g_ord[J];                  // sorted pos p -> true column j
__device__ int      g_nt[3 * J];               // per-third nnz  [s][p]
__device__ uint2    g_meta[3 * TCAP * J];      // per-third ELL [s][e][p]:
                                               //   .x = local gene idx, .y = val bits

__device__ __constant__ int c_base[3] = {0, SEG0, SEG0 + SEG1};
__device__ __constant__ int c_len[3]  = {SEG0, SEG1, SEG2};

// ---------------------------------------------------------------------------
// 0. zero counters + histogram
// ---------------------------------------------------------------------------
__global__ void k_zero() {
    int i = blockIdx.x * blockDim.x + threadIdx.x;
    if (i < J)  g_cnt[i]  = 0;
    if (i < NB) g_hist[i] = 0;
}

// ---------------------------------------------------------------------------
// 1. Scan dense mask -> unsorted ELL (gathering masked weights).
//    density 0.08% -> inner branch almost never executes. Streaming loads
//    (__ldcs) keep this 400 MB single-use scan from evicting L2 state.
// ---------------------------------------------------------------------------
__global__ void k_build(const float4* __restrict__ mask4,
                        const float*  __restrict__ weight) {
    const int64_t total4 = (int64_t)G * J / 4;   // 25,000,000
    int64_t t = (int64_t)blockIdx.x * blockDim.x + threadIdx.x;
    if (t >= total4) return;
    float4 m = __ldcs(mask4 + t);
    if (m.x == 0.f && m.y == 0.f && m.z == 0.f && m.w == 0.f) return;
    int64_t base = t * 4;
    float mv[4] = {m.x, m.y, m.z, m.w};
#pragma unroll
    for (int c = 0; c < 4; c++) {
        if (mv[c] != 0.f) {
            int64_t idx = base + c;
            int i = (int)(idx / J);
            int j = (int)(idx - (int64_t)i * J);
            int slot = atomicAdd(&g_cnt[j], 1);
            if (slot < CAP) {
                g_idx_u[slot * J + j] = (uint16_t)i;
                g_val_u[slot * J + j] = weight[idx];
            }
        }
    }
}

// ---------------------------------------------------------------------------
// 2. counting sort of columns by nnz (descending) -> warp-uniform work.
//    Column order only changes thread ownership, never output values.
// ---------------------------------------------------------------------------
__global__ void k_hist() {
    int j = blockIdx.x * blockDim.x + threadIdx.x;
    if (j < J) atomicAdd(&g_hist[min(g_cnt[j], CAP)], 1);
}
__global__ void k_scan() {
    if (threadIdx.x == 0) {
        int acc = 0;
        for (int n = CAP; n >= 0; n--) { g_off[n] = acc; acc += g_hist[n]; }
    }
}
__global__ void k_scatter() {
    int j = blockIdx.x * blockDim.x + threadIdx.x;
    if (j < J) {
        int n = min(g_cnt[j], CAP);
        int p = atomicAdd(&g_off[n], 1);
        g_ord[p] = j;
    }
}

// ---------------------------------------------------------------------------
// 3. repack into per-third packed ELLs in sorted-column order. Entries within
//    each column sorted by gene index -> deterministic accumulation order
//    (thirds processed in order preserve ascending-gene order globally).
//    Indices stored local to their segment; idx+val packed in one uint2.
// ---------------------------------------------------------------------------
__global__ void k_repack() {
    int p = blockIdx.x * blockDim.x + threadIdx.x;
    if (p >= J) return;
    int j = g_ord[p];
    int n = min(g_cnt[j], CAP);
    int   li[CAP];
    float lv[CAP];
    for (int e = 0; e < n; e++) {
        li[e] = g_idx_u[e * J + j];
        lv[e] = g_val_u[e * J + j];
    }
    for (int a = 1; a < n; a++) {            // insertion sort by gene index
        int ki = li[a]; float kv = lv[a];
        int q = a - 1;
        while (q >= 0 && li[q] > ki) { li[q+1] = li[q]; lv[q+1] = lv[q]; q--; }
        li[q+1] = ki; lv[q+1] = kv;
    }
    int es[3] = {0, 0, 0};
    for (int e = 0; e < n; e++) {
        int s = (li[e] >= SEG0 + SEG1) ? 2 : ((li[e] >= SEG0) ? 1 : 0);
        int slot = es[s]++;
        if (slot < TCAP) {
            g_meta[(s * TCAP + slot) * J + p] =
                make_uint2((unsigned)(li[e] - c_base[s]), __float_as_uint(lv[e]));
        }
    }
#pragma unroll
    for (int s = 0; s < 3; s++) g_nt[s * J + p] = min(es[s], TCAP);
}

// ---------------------------------------------------------------------------
// 4. SpMM: block owns 4 batch rows; three gene-third passes. The 4 rows are
//    interleaved in smem as float4 (sx4[i] = {x0[i],x1[i],x2[i],x3[i]}) so
//    each nnz entry costs ONE LDS.128 + ONE LDG.64 (packed meta). 104 KB
//    smem -> 2 CTAs/SM: one CTA's DRAM fill overlaps the other's gather.
//    All single-use streams (x in, out) use streaming/no-allocate hints so
//    the ~540 KB packed ELL stays L2-resident across all 1024 CTAs.
// ---------------------------------------------------------------------------
__global__ void __launch_bounds__(TPB, 2)
k_spmm(const float* __restrict__ x, float* __restrict__ out) {
    extern __shared__ float sm[];            // SEGMAX float4
    float4* sx4 = (float4*)sm;

    const int b0  = blockIdx.x * RPB;
    const int tid = threadIdx.x;

    float acc[CPT][RPB];
#pragma unroll
    for (int c = 0; c < CPT; c++)
#pragma unroll
        for (int r = 0; r < RPB; r++) acc[c][r] = 0.f;

    const float* x0 = x + (size_t)(b0 + 0) * G;
    const float* x1 = x + (size_t)(b0 + 1) * G;
    const float* x2 = x + (size_t)(b0 + 2) * G;
    const float* x3 = x + (size_t)(b0 + 3) * G;

#pragma unroll
    for (int s = 0; s < 3; s++) {
        if (s) __syncthreads();              // previous pass done reading sm
        const int base = c_base[s];
        const int len2 = c_len[s] / 2;       // float2 pairs (all lens even)

        // fill phase: float2 per row (LDG.64, streaming), register-transpose
        // into two float4 smem slots. Consecutive lanes -> consecutive slots.
        {
            const float2* p0 = (const float2*)(x0 + base);
            const float2* p1 = (const float2*)(x1 + base);
            const float2* p2 = (const float2*)(x2 + base);
            const float2* p3 = (const float2*)(x3 + base);
            for (int i2 = tid; i2 < len2; i2 += TPB) {
                float2 a0 = __ldcs(p0 + i2);
                float2 a1 = __ldcs(p1 + i2);
                float2 a2 = __ldcs(p2 + i2);
                float2 a3 = __ldcs(p3 + i2);
                sx4[2 * i2 + 0] = make_float4(a0.x, a1.x, a2.x, a3.x);
                sx4[2 * i2 + 1] = make_float4(a0.y, a1.y, a2.y, a3.y);
            }
        }
        __syncthreads();

        // gather phase
#pragma unroll
        for (int c = 0; c < CPT; c++) {
            const int p = tid + c * TPB;
            if (p < J) {
                const int n = g_nt[s * J + p];
                const uint2* mp = g_meta + (size_t)(s * TCAP) * J + p;
#pragma unroll 4
                for (int e = 0; e < n; e++) {
                    const uint2 md = __ldg(mp);
                    mp += J;
                    const float w = __uint_as_float(md.y);
                    const float4 xv = sx4[md.x];
                    acc[c][0] += w * xv.x;
                    acc[c][1] += w * xv.y;
                    acc[c][2] += w * xv.z;
                    acc[c][3] += w * xv.w;
                }
            }
        }
    }

    // stage output in smem (reuse x area: RPB*J*4 = 80 KB <= 104 KB)
    __syncthreads();
#pragma unroll
    for (int c = 0; c < CPT; c++) {
        const int p = tid + c * TPB;
        if (p < J) {
            const int j = g_ord[p];
#pragma unroll
            for (int r = 0; r < RPB; r++) sm[r * J + j] = acc[c][r];
        }
    }
    __syncthreads();

    // coalesced float4 writeout; write-through (no L2 allocate) — output is
    // single-use and must not evict the L2-resident metadata.
#pragma unroll 2
    for (int t = tid; t < RPB * (J / 4); t += TPB) {
        const int r = t / (J / 4);
        const int q = t - r * (J / 4);
        __stwt((float4*)(out + (size_t)(b0 + r) * J) + q,
               ((const float4*)(sm + r * J))[q]);
    }
}

// ---------------------------------------------------------------------------
extern "C" void kernel_launch(void* const* d_in, const int* in_sizes, int n_in,
                              void* d_out, int out_size) {
    const float* x      = (const float*)d_in[0];  // [B, G]
    const float* weight = (const float*)d_in[1];  // [G, J]
    const float* mask   = (const float*)d_in[2];  // [G, J]
    float* out = (float*)d_out;                   // [B, J]

    cudaFuncSetAttribute(k_spmm, cudaFuncAttributeMaxDynamicSharedMemorySize,
                         SMEM_BYTES);

    k_zero<<<(J + 255) / 256, 256>>>();
    {
        int64_t total4 = (int64_t)G * J / 4;
        k_build<<<(int)((total4 + 255) / 256), 256>>>((const float4*)mask, weight);
    }
    k_hist<<<(J + 255) / 256, 256>>>();
    k_scan<<<1, 32>>>();
    k_scatter<<<(J + 255) / 256, 256>>>();
    k_repack<<<(J + 255) / 256, 256>>>();
    k_spmm<<<B / RPB, TPB, SMEM_BYTES>>>(x, out);
}

// round 15
// speedup vs baseline: 1.0107x; 1.0107x over previous
#include <cuda_runtime.h>
#include <cstdint>

// Problem constants (fixed by the reference)
#define B 4096      // batch
#define G 20000     // genes (K)
#define J 5000      // GO terms (N)
#define CAP 64      // max nnz per column overall (~Poisson(16), max ~40)
#define TCAP 32     // max nnz per column per gene-third (~Poisson(5.3))
#define PE (TCAP / 2)                // metadata pairs per column per third

// gene segments: [0,6672) [6672,13344) [13344,20000)
#define SEG0 6672
#define SEG1 6672
#define SEG2 6656
#define SEGMAX 6672

#define TPB 512
#define RPB 4                        // batch rows per SpMM block
#define CPT 10                       // ceil(J / TPB); first 9 are full
#define SMEM_BYTES (SEGMAX * 16)     // 106,752 B -> 2 CTAs/SM

// Static device scratch (no allocation allowed anywhere)
__device__ int      g_cnt[J];
__device__ uint2    g_u[CAP * J];              // unsorted ELL [e][j]: (gene, val bits)
__device__ int      g_np[3 * J];               // per-third PAIR count [s][j]
__device__ uint4    g_meta[3 * PE * J];        // per-third paired ELL [s][e2][j]:
                                               //  (idx0, val0_bits, idx1, val1_bits)

__device__ __constant__ int c_base[3] = {0, SEG0, SEG0 + SEG1};
__device__ __constant__ int c_len[3]  = {SEG0, SEG1, SEG2};

// ---------------------------------------------------------------------------
// 0. zero per-column counters
// ---------------------------------------------------------------------------
__global__ void k_zero() {
    int i = blockIdx.x * blockDim.x + threadIdx.x;
    if (i < J) g_cnt[i] = 0;
}

// ---------------------------------------------------------------------------
// 1. Scan dense mask -> unsorted ELL (gathering masked weights).
//    2D grid: blockIdx.y = gene row -> i and j from block coords, all 32-bit,
//    no divisions. density 0.08% -> inner branch almost never executes.
//    __ldcs keeps this 400 MB single-use scan from evicting L2 state.
// ---------------------------------------------------------------------------
__global__ void k_build(const float4* __restrict__ mask4,
                        const float*  __restrict__ weight) {
    const int i = blockIdx.y;                              // gene row
    const int q = blockIdx.x * blockDim.x + threadIdx.x;   // float4 idx in row
    if (q >= J / 4) return;
    const int row = i * J;                                 // < 1e8, fits int32
    float4 m = __ldcs(mask4 + (row >> 2) + q);
    if (m.x == 0.f && m.y == 0.f && m.z == 0.f && m.w == 0.f) return;
    float mv[4] = {m.x, m.y, m.z, m.w};
#pragma unroll
    for (int c = 0; c < 4; c++) {
        if (mv[c] != 0.f) {
            int j = q * 4 + c;
            int slot = atomicAdd(&g_cnt[j], 1);
            if (slot < CAP) {
                g_u[slot * J + j] =
                    make_uint2((unsigned)i, __float_as_uint(weight[row + j]));
            }
        }
    }
}

// ---------------------------------------------------------------------------
// 2. repack: thread per column j (natural order). Sorts the column's entries
//    by gene index (deterministic accumulation order despite atomic build;
//    thirds processed in order preserve global ascending order), then writes
//    the per-third PAIRED ELL (2 entries per uint4). Odd counts padded with
//    (idx=0, val=0.0f) -> contributes exactly 0.
// ---------------------------------------------------------------------------
__global__ void k_repack() {
    int j = blockIdx.x * blockDim.x + threadIdx.x;
    if (j >= J) return;
    int n = min(g_cnt[j], CAP);

    int   li[CAP];
    float lv[CAP];
    for (int e = 0; e < n; e++) {
        uint2 u = g_u[e * J + j];
        li[e] = (int)u.x;
        lv[e] = __uint_as_float(u.y);
    }
    for (int a = 1; a < n; a++) {            // insertion sort by gene index
        int ki = li[a]; float kv = lv[a];
        int q = a - 1;
        while (q >= 0 && li[q] > ki) { li[q+1] = li[q]; lv[q+1] = lv[q]; q--; }
        li[q+1] = ki; lv[q+1] = kv;
    }
    int   si[3][TCAP];
    float sv[3][TCAP];
    int es[3] = {0, 0, 0};
    for (int e = 0; e < n; e++) {
        int s = (li[e] >= SEG0 + SEG1) ? 2 : ((li[e] >= SEG0) ? 1 : 0);
        int slot = es[s]++;
        if (slot < TCAP) {
            si[s][slot] = li[e] - c_base[s];
            sv[s][slot] = lv[e];
        }
    }
#pragma unroll
    for (int s = 0; s < 3; s++) {
        int ns = min(es[s], TCAP);
        int np = (ns + 1) / 2;
        for (int e2 = 0; e2 < np; e2++) {
            int e0 = 2 * e2, e1 = 2 * e2 + 1;
            uint4 md;
            md.x = (unsigned)si[s][e0];
            md.y = __float_as_uint(sv[s][e0]);
            md.z = (e1 < ns) ? (unsigned)si[s][e1] : 0u;
            md.w = (e1 < ns) ? __float_as_uint(sv[s][e1]) : 0u;
            g_meta[(s * PE + e2) * J + j] = md;
        }
        g_np[s * J + j] = np;
    }
}

// ---------------------------------------------------------------------------
// helper: gather one column's entries for the current segment
// ---------------------------------------------------------------------------
__device__ __forceinline__ void gather_col(const float4* __restrict__ sx4,
                                           int s, int j, float* __restrict__ a) {
    const int np = g_np[s * J + j];
    const uint4* mp = g_meta + (size_t)(s * PE) * J + j;
#pragma unroll 4
    for (int e2 = 0; e2 < np; e2++) {
        const uint4 md = __ldg(mp);
        mp += J;
        const float  w0  = __uint_as_float(md.y);
        const float4 xv0 = sx4[md.x];
        a[0] += w0 * xv0.x;
        a[1] += w0 * xv0.y;
        a[2] += w0 * xv0.z;
        a[3] += w0 * xv0.w;
        const float  w1  = __uint_as_float(md.w);
        const float4 xv1 = sx4[md.z];
        a[0] += w1 * xv1.x;
        a[1] += w1 * xv1.y;
        a[2] += w1 * xv1.z;
        a[3] += w1 * xv1.w;
    }
}

// ---------------------------------------------------------------------------
// 3. SpMM: block owns 4 batch rows; three gene-third passes. The 4 rows are
//    interleaved in smem as float4 (sx4[i] = {x0[i],x1[i],x2[i],x3[i]}) so
//    each nnz entry costs ONE LDS.128; metadata comes 2 entries per LDG.128.
//    104 KB smem -> 2 CTAs/SM: one CTA's DRAM fill overlaps the other's
//    gather. First 9 column iterations are unguarded (tid + c*512 < 5000
//    for c < 9); only the last is predicated. Output written directly,
//    coalesced STG.32 write-through (single-use, must not evict metadata).
// ---------------------------------------------------------------------------
__global__ void __launch_bounds__(TPB, 2)
k_spmm(const float* __restrict__ x, float* __restrict__ out) {
    extern __shared__ float sm[];            // SEGMAX float4
    float4* sx4 = (float4*)sm;

    const int b0  = blockIdx.x * RPB;
    const int tid = threadIdx.x;
    const int jt  = tid + 9 * TPB;           // tail column (may be >= J)

    float acc[CPT][RPB];
#pragma unroll
    for (int c = 0; c < CPT; c++)
#pragma unroll
        for (int r = 0; r < RPB; r++) acc[c][r] = 0.f;

    const float* x0 = x + (size_t)(b0 + 0) * G;
    const float* x1 = x + (size_t)(b0 + 1) * G;
    const float* x2 = x + (size_t)(b0 + 2) * G;
    const float* x3 = x + (size_t)(b0 + 3) * G;

#pragma unroll
    for (int s = 0; s < 3; s++) {
        if (s) __syncthreads();              // previous pass done reading sm
        const int base = c_base[s];
        const int len2 = c_len[s] / 2;       // float2 pairs (all lens even)

        // fill phase: float2 per row (LDG.64, streaming), register-transpose
        // into two float4 smem slots. Consecutive lanes -> consecutive slots.
        {
            const float2* p0 = (const float2*)(x0 + base);
            const float2* p1 = (const float2*)(x1 + base);
            const float2* p2 = (const float2*)(x2 + base);
            const float2* p3 = (const float2*)(x3 + base);
            for (int i2 = tid; i2 < len2; i2 += TPB) {
                float2 a0 = __ldcs(p0 + i2);
                float2 a1 = __ldcs(p1 + i2);
                float2 a2 = __ldcs(p2 + i2);
                float2 a3 = __ldcs(p3 + i2);
                sx4[2 * i2 + 0] = make_float4(a0.x, a1.x, a2.x, a3.x);
                sx4[2 * i2 + 1] = make_float4(a0.y, a1.y, a2.y, a3.y);
            }
        }
        __syncthreads();

        // gather phase: 9 unguarded columns + 1 predicated tail
#pragma unroll
        for (int c = 0; c < 9; c++)
            gather_col(sx4, s, tid + c * TPB, acc[c]);
        if (jt < J)
            gather_col(sx4, s, jt, acc[9]);
    }

    // direct writeout: thread tid owns columns tid + c*TPB -> consecutive
    // lanes write consecutive addresses (coalesced). Write-through, no L2
    // allocate — output is single-use and must not evict metadata.
#pragma unroll
    for (int c = 0; c < 9; c++) {
        const int j = tid + c * TPB;
#pragma unroll
        for (int r = 0; r < RPB; r++)
            __stwt(out + (size_t)(b0 + r) * J + j, acc[c][r]);
    }
    if (jt < J) {
#pragma unroll
        for (int r = 0; r < RPB; r++)
            __stwt(out + (size_t)(b0 + r) * J + jt, acc[9][r]);
    }
}

// ---------------------------------------------------------------------------
extern "C" void kernel_launch(void* const* d_in, const int* in_sizes, int n_in,
                              void* d_out, int out_size) {
    const float* x      = (const float*)d_in[0];  // [B, G]
    const float* weight = (const float*)d_in[1];  // [G, J]
    const float* mask   = (const float*)d_in[2];  // [G, J]
    float* out = (float*)d_out;                   // [B, J]

    cudaFuncSetAttribute(k_spmm, cudaFuncAttributeMaxDynamicSharedMemorySize,
                         SMEM_BYTES);

    k_zero<<<(J + 255) / 256, 256>>>();                                   // 0
    {
        dim3 grid((J / 4 + 511) / 512, G);   // 3 x 20000 blocks, 512 thr
        k_build<<<grid, 512>>>((const float4*)mask, weight);              // 1
    }
    k_repack<<<(J + 255) / 256, 256>>>();                                 // 2
    k_spmm<<<B / RPB, TPB, SMEM_BYTES>>>(x, out);                         // 3
}